// round 14
// baseline (speedup 1.0000x reference)
#include <cuda_runtime.h>
#include <cuda_bf16.h>

#define Bz 32
#define Nn 384          // H*W = 12*32
#define Cc 512
#define Dd 512
#define Ee 256
#define Vv 600
#define GJ 2048         // 4*D
#define NSTEP 191
#define EOS_TOK 130

// ----------------------------- scratch (device globals, no allocation) ------
__device__ float g_Wv[Bz * Nn * Dd];          // 24 MB   enc @ W_v, precomputed
__device__ float g_gp[8 * Bz * GJ];           // gates partials [ks][b][2048]
__device__ float g_op[8 * Bz * Dd];           // o_t partials [ks][b][d]
__device__ float g_xT[1280 * Bz];             // transposed x: [emb|oprev|hx][b]
__device__ float g_cx[Bz * Dd];
__device__ float g_q[Bz * Dd];
__device__ float g_ctxT[Cc * Bz];             // transposed UNNORMALIZED ctx [c][b]
__device__ float g_sum[Bz];                   // per-b softmax denominator
__device__ float g_sc[Bz * Nn];               // exp(score) values
__device__ int   g_tok[NSTEP * Bz];

// grid barrier state
__device__ unsigned g_count = 0;
__device__ volatile unsigned g_gen = 0;

// fast transcendentals
__device__ __forceinline__ float tanh_mufu(float x) {      // 1 MUFU, abs err ~5e-4
    float y;
    asm("tanh.approx.f32 %0, %1;" : "=f"(y) : "f"(x));
    return y;
}
__device__ __forceinline__ float tanh_fast(float x) {      // 2 MUFU, err ~1e-7
    float e = __expf(-2.0f * x);
    return __fdividef(2.0f, 1.0f + e) - 1.0f;
}
__device__ __forceinline__ float sig_fast(float x) {
    return __fdividef(1.0f, 1.0f + __expf(-x));
}

__device__ __forceinline__ void gsync(int nblk) {
    __syncthreads();
    if (threadIdx.x == 0) {
        __threadfence();
        unsigned gen = g_gen;
        unsigned t = atomicInc(&g_count, (unsigned)(nblk - 1)); // wraps at nblk-1
        if (t == (unsigned)(nblk - 1)) {
            __threadfence();
            g_gen = gen + 1;                 // release
        } else {
            while (g_gen == gen) { }         // spin (volatile load)
            __threadfence();                 // acquire
        }
    }
    __syncthreads();
}

// ============================ the whole decoder ==============================
__global__ void __launch_bounds__(256, 2) k_all(
    const float* __restrict__ enc, const int* __restrict__ tgt,
    const float* __restrict__ emb,
    const float* __restrict__ Wih, const float* __restrict__ bih,
    const float* __restrict__ Whh, const float* __restrict__ bhh,
    const float* __restrict__ Wh,  const float* __restrict__ Wvw,
    const float* __restrict__ vvec,
    const float* __restrict__ Wc,  const float* __restrict__ bc,
    const float* __restrict__ Wout,const float* __restrict__ bout,
    float* __restrict__ out_logits, float* __restrict__ out_alpha, int nblk)
{
    __shared__ float sh[6144];                       // 24 KB, reused per phase
    const int tid = threadIdx.x;
    const int bid = blockIdx.x;

    // -------------------- prologue: Wv GEMM + init + tokens -----------------
    for (int job = bid; job < 399; job += nblk) {
        if (job < 384) {
            int bm = job >> 2, bn = job & 3;
            int tm = tid / 16, tn = tid % 16;
            float acc[8][8];
#pragma unroll
            for (int i = 0; i < 8; i++)
#pragma unroll
                for (int j = 0; j < 8; j++) acc[i][j] = 0.0f;
            const float* Ag = enc + (size_t)(bm * 128) * 512;
            const float* Bg = Wvw + bn * 128;
            float* As = sh;            // [8][128]
            float* Bs = sh + 1024;     // [8][128]
            for (int k0 = 0; k0 < 512; k0 += 8) {
                {
                    int r = tid >> 1, s = tid & 1;
                    float4 a = *(const float4*)(Ag + (size_t)r * 512 + k0 + s * 4);
                    As[(s * 4 + 0) * 128 + r] = a.x; As[(s * 4 + 1) * 128 + r] = a.y;
                    As[(s * 4 + 2) * 128 + r] = a.z; As[(s * 4 + 3) * 128 + r] = a.w;
                }
                {
                    int kk = tid >> 5, c4 = tid & 31;
                    float4 bv = *(const float4*)(Bg + (size_t)(k0 + kk) * 512 + c4 * 4);
                    *(float4*)&Bs[kk * 128 + c4 * 4] = bv;
                }
                __syncthreads();
#pragma unroll
                for (int kk = 0; kk < 8; kk++) {
                    float a[8], b[8];
                    *(float4*)(a)     = *(float4*)&As[kk * 128 + tm * 8];
                    *(float4*)(a + 4) = *(float4*)&As[kk * 128 + tm * 8 + 4];
                    *(float4*)(b)     = *(float4*)&Bs[kk * 128 + tn * 8];
                    *(float4*)(b + 4) = *(float4*)&Bs[kk * 128 + tn * 8 + 4];
#pragma unroll
                    for (int i = 0; i < 8; i++)
#pragma unroll
                        for (int j = 0; j < 8; j++) acc[i][j] += a[i] * b[j];
                }
                __syncthreads();
            }
            float* Cg = g_Wv + (size_t)(bm * 128) * 512 + bn * 128;
#pragma unroll
            for (int i = 0; i < 8; i++) {
                int r = tm * 8 + i;
#pragma unroll
                for (int j = 0; j < 8; j += 4) {
                    float4 o = make_float4(acc[i][j], acc[i][j+1], acc[i][j+2], acc[i][j+3]);
                    *(float4*)(Cg + (size_t)r * 512 + tn * 8 + j) = o;
                }
            }
        } else if (job == 384) {
            // token precompute (int64/int32 autodetect: int64 high words are 0)
            if (tid == 0) {
                int nz = 0;
                for (int i = 1; i < 64; i += 2) nz |= tgt[i];
                ((int*)sh)[0] = (nz == 0) ? 1 : 0;
            }
            __syncthreads();
            int is64 = ((int*)sh)[0];
            if (tid < Bz) {
                int b = tid, fin = 0;
                g_tok[b] = 0;                         // sos
                for (int t = 0; t < NSTEP - 1; t++) {
                    int idx = b * 192 + t + 1;
                    int nt = is64 ? tgt[idx * 2] : tgt[idx];
                    fin |= (nt == EOS_TOK);
                    g_tok[(t + 1) * Bz + b] = fin ? 0 : nt;
                }
            }
        } else {
            int base = (job - 385) * 4096;            // 14 jobs x 4096 = 57344
            for (int i = tid; i < 4096; i += 256) {
                int idx = base + i;
                if (idx < 40960)        g_xT[idx] = 0.0f;   // emb(0)=0, oprev=0, hx=0
                else if (idx < 57344)   g_cx[idx - 40960] = 0.0f;
            }
        }
        __syncthreads();
    }
    gsync(nblk);

    // ============================== step loop ===============================
    for (int t = 0; t < NSTEP; t++) {

        // ---- gates split-K GEMM: 256 jobs (32 jt x 8 ks), 4j-wide ----
        for (int job = bid; job < 256; job += nblk) {
            int jt = job & 31, ks = job >> 5;
            int kbase, klen;
            if (ks < 4) { kbase = ks * 192;             klen = 192; }
            else        { kbase = 768 + (ks - 4) * 128; klen = 128; }
            float* xs = sh;                            // [klen][32]
            for (int i4 = tid; i4 < klen * 8; i4 += 256) {
                int kk = i4 >> 3, b4 = i4 & 7;
                float4 v = ((const float4*)(g_xT + (size_t)(kbase + kk) * 32))[b4];
                ((float4*)(xs + kk * 32))[b4] = v;
            }
            __syncthreads();
            int jg = tid & 15, bq = tid >> 4;          // 4 j each, 2 b each
            int j = jt * 64 + jg * 4;
            const float* Wbase = (ks < 4) ? (Wih + (size_t)kbase * GJ + j)
                                          : (Whh + (size_t)(kbase - 768) * GJ + j);
            const float4* Wp4 = (const float4*)Wbase;
            float a0x=0,a0y=0,a0z=0,a0w=0, a1x=0,a1y=0,a1z=0,a1w=0;
#pragma unroll 16
            for (int kk = 0; kk < klen; kk++) {
                float4 w = Wp4[(size_t)kk * (GJ / 4)];
                float2 x = *(const float2*)&xs[kk * 32 + bq * 2];
                a0x += x.x * w.x; a0y += x.x * w.y; a0z += x.x * w.z; a0w += x.x * w.w;
                a1x += x.y * w.x; a1y += x.y * w.y; a1z += x.y * w.z; a1w += x.y * w.w;
            }
            *(float4*)&g_gp[((size_t)ks * Bz + bq * 2 + 0) * GJ + j] = make_float4(a0x,a0y,a0z,a0w);
            *(float4*)&g_gp[((size_t)ks * Bz + bq * 2 + 1) * GJ + j] = make_float4(a1x,a1y,a1z,a1w);
            __syncthreads();
        }
        gsync(nblk);

        // ---- LSTM elementwise + zero q/ctxT/sum, write hxT ----
        for (int idx = bid * 256 + tid; idx < 16384; idx += nblk * 256) {
            int d = idx & 511;
            int b = idx >> 9;
            float gi = bih[d] + bhh[d];
            float gf = bih[d + 512] + bhh[d + 512];
            float gg = bih[d + 1024] + bhh[d + 1024];
            float go = bih[d + 1536] + bhh[d + 1536];
#pragma unroll
            for (int s = 0; s < 8; s++) {
                const float* gp = g_gp + ((size_t)s * Bz + b) * GJ;
                gi += gp[d];
                gf += gp[d + 512];
                gg += gp[d + 1024];
                go += gp[d + 1536];
            }
            float c = g_cx[idx];
            c = sig_fast(gf) * c + sig_fast(gi) * tanh_fast(gg);
            float h = sig_fast(go) * tanh_fast(c);
            g_cx[idx] = c;
            g_xT[(768 + d) * 32 + b] = h;            // transposed hx
            g_q[idx] = 0.0f;
            g_ctxT[idx] = 0.0f;
            if (idx < 32) g_sum[idx] = 0.0f;
        }
        gsync(nblk);

        // ---- q = hx @ W_h: 128 jobs (8 dt x 16 ks of K=32), atomic accum ----
        for (int job = bid; job < 128; job += nblk) {
            int dt = job & 7, ks = job >> 3;
            float* xs = sh;                            // [32][32]
            {
                int kk = tid >> 3, b4 = tid & 7;
                float4 v = ((const float4*)(g_xT + (size_t)(768 + ks * 32 + kk) * 32))[b4];
                ((float4*)(xs + kk * 32))[b4] = v;
            }
            __syncthreads();
            int dl = tid & 63, bq = tid >> 6;
            int d = dt * 64 + dl;
            const float* Wp = Wh + (size_t)(ks * 32) * Dd + d;
            float acc[8];
#pragma unroll
            for (int i = 0; i < 8; i++) acc[i] = 0.0f;
#pragma unroll 16
            for (int kk = 0; kk < 32; kk++) {
                float w = Wp[(size_t)kk * Dd];
                float4 x0 = *(float4*)&xs[kk * 32 + bq * 8];
                float4 x1 = *(float4*)&xs[kk * 32 + bq * 8 + 4];
                acc[0] += w * x0.x; acc[1] += w * x0.y; acc[2] += w * x0.z; acc[3] += w * x0.w;
                acc[4] += w * x1.x; acc[5] += w * x1.y; acc[6] += w * x1.z; acc[7] += w * x1.w;
            }
#pragma unroll
            for (int i = 0; i < 8; i++)
                atomicAdd(&g_q[(bq * 8 + i) * Dd + d], acc[i]);
            __syncthreads();
        }
        gsync(nblk);

        // ---- scores + exp + unnormalized context: 608 jobs (19 nt x 32 b) ----
        for (int job = bid; job < 608; job += nblk) {
            int nt = job % 19, b = job / 19;
            float* qs = sh;                            // 512
            float* vs = sh + 512;                      // 512
            float* sctx = sh + 1024;                   // 512
            qs[tid] = g_q[b * Dd + tid];
            qs[tid + 256] = g_q[b * Dd + tid + 256];
            vs[tid] = vvec[tid];
            vs[tid + 256] = vvec[tid + 256];
            sctx[tid] = 0.0f;
            sctx[tid + 256] = 0.0f;
            if (tid == 0) sh[1536] = 0.0f;
            __syncthreads();
            int w = tid >> 5, lane = tid & 31;
            int n0 = nt * 20;
            int cnt = (nt == 18) ? 24 : 20;
            const float4* q4 = (const float4*)qs;
            const float4* v4 = (const float4*)vs;
            float4 ca0 = make_float4(0,0,0,0), ca1 = ca0, ca2 = ca0, ca3 = ca0;
            float e_sum = 0.0f;
            for (int r = w; r < cnt; r += 8) {
                int n = n0 + r;
                const float4* wv = (const float4*)(g_Wv + (size_t)(b * Nn + n) * Dd);
                float acc = 0.0f;
#pragma unroll
                for (int i = 0; i < 4; i++) {
                    int id = i * 32 + lane;
                    float4 a = wv[id], q = q4[id], v = v4[id];
                    acc += tanh_mufu(a.x + q.x) * v.x;
                    acc += tanh_mufu(a.y + q.y) * v.y;
                    acc += tanh_mufu(a.z + q.z) * v.z;
                    acc += tanh_mufu(a.w + q.w) * v.w;
                }
#pragma unroll
                for (int off = 16; off > 0; off >>= 1)
                    acc += __shfl_xor_sync(0xffffffffu, acc, off);
                float e = __expf(acc);                 // bounded: |acc| <~ 20
                if (lane == 0) g_sc[b * Nn + n] = e;
                e_sum += e;
                const float4* ep = (const float4*)(enc + (size_t)(b * Nn + n) * Cc);
                float4 e0 = ep[lane], e1 = ep[32 + lane], e2 = ep[64 + lane], e3 = ep[96 + lane];
                ca0.x += e * e0.x; ca0.y += e * e0.y; ca0.z += e * e0.z; ca0.w += e * e0.w;
                ca1.x += e * e1.x; ca1.y += e * e1.y; ca1.z += e * e1.z; ca1.w += e * e1.w;
                ca2.x += e * e2.x; ca2.y += e * e2.y; ca2.z += e * e2.z; ca2.w += e * e2.w;
                ca3.x += e * e3.x; ca3.y += e * e3.y; ca3.z += e * e3.z; ca3.w += e * e3.w;
            }
            {   // flush warp partials into smem
                int c0 = lane * 4;
                atomicAdd(&sctx[c0 + 0], ca0.x); atomicAdd(&sctx[c0 + 1], ca0.y);
                atomicAdd(&sctx[c0 + 2], ca0.z); atomicAdd(&sctx[c0 + 3], ca0.w);
                atomicAdd(&sctx[512 - 384 + 128 + c0 + 0], 0.0f); // (no-op keep layout simple)
                int c1 = 128 + lane * 4;
                atomicAdd(&sctx[c1 + 0], ca1.x); atomicAdd(&sctx[c1 + 1], ca1.y);
                atomicAdd(&sctx[c1 + 2], ca1.z); atomicAdd(&sctx[c1 + 3], ca1.w);
                int c2 = 256 + lane * 4;
                atomicAdd(&sctx[c2 + 0], ca2.x); atomicAdd(&sctx[c2 + 1], ca2.y);
                atomicAdd(&sctx[c2 + 2], ca2.z); atomicAdd(&sctx[c2 + 3], ca2.w);
                int c3 = 384 + lane * 4;
                atomicAdd(&sctx[c3 + 0], ca3.x); atomicAdd(&sctx[c3 + 1], ca3.y);
                atomicAdd(&sctx[c3 + 2], ca3.z); atomicAdd(&sctx[c3 + 3], ca3.w);
                if (lane == 0) atomicAdd(&sh[1536], e_sum);
            }
            __syncthreads();
            atomicAdd(&g_ctxT[(size_t)tid * 32 + b], sctx[tid]);
            atomicAdd(&g_ctxT[(size_t)(tid + 256) * 32 + b], sctx[tid + 256]);
            if (tid == 0) atomicAdd(&g_sum[b], sh[1536]);
            __syncthreads();
        }
        gsync(nblk);

        // ---- o_t partials (normalized ctx) + bias init + alpha: 211 jobs ----
        for (int job = bid; job < 211; job += nblk) {
            if (job < 128) {
                // (dt 0..7, ks 0..7, bh 0..1): 16 b per job, K=128, 4d-wide
                float* xs = sh;                        // [128][16]
                float* sinv = sh + 2048;               // [16]
                int dt = job & 7, ks = (job >> 3) & 7, bh = job >> 6;
                if (tid < 16) sinv[tid] = __fdividef(1.0f, g_sum[bh * 16 + tid]);
                __syncthreads();
                for (int i = tid; i < 2048; i += 256) {
                    int kk = i >> 4, b4 = i & 15;
                    int k = ks * 128 + kk;
                    float val;
                    if (k < 512) val = g_xT[(size_t)(768 + k) * 32 + bh * 16 + b4];
                    else         val = g_ctxT[(size_t)(k - 512) * 32 + bh * 16 + b4] * sinv[b4];
                    xs[kk * 16 + b4] = val;
                }
                __syncthreads();
                int jg = tid & 15, bq = tid >> 4;      // 4 d each, 1 b each (16 b)
                int d = dt * 64 + jg * 4;
                const float4* Wp4 = (const float4*)(Wc + (size_t)(ks * 128) * Dd + d);
                float ax = 0, ay = 0, az = 0, aw = 0;
#pragma unroll 16
                for (int kk = 0; kk < 128; kk++) {
                    float4 w = Wp4[(size_t)kk * (Dd / 4)];
                    float x = xs[kk * 16 + bq];
                    ax += x * w.x; ay += x * w.y; az += x * w.z; aw += x * w.w;
                }
                *(float4*)&g_op[((size_t)ks * Bz + bh * 16 + bq) * Dd + d] =
                    make_float4(ax, ay, az, aw);
            } else if (job < 203) {
                int idx = (job - 128) * 256 + tid;     // < 32*600 = 19200
                if (idx < Bz * Vv) {
                    int b = idx / Vv, v = idx % Vv;
                    out_logits[((size_t)b * NSTEP + t) * Vv + v] = bout[v];
                }
            } else {
                // alpha = e / sum : 8 jobs x 4 b
                int jb = job - 203;
                for (int i = tid; i < 4 * Nn; i += 256) {
                    int b = jb * 4 + i / Nn, n = i % Nn;
                    out_alpha[((size_t)b * NSTEP + t) * Nn + n] =
                        __fdividef(g_sc[b * Nn + n], g_sum[b]);
                }
            }
            __syncthreads();
        }
        gsync(nblk);

        // ---- logits + o_prevT persist + embT(t+1) prefetch: 168 jobs ----
        for (int job = bid; job < 168; job += nblk) {
            if (job >= 160) {
                if (t + 1 < NSTEP) {
                    int j8 = job - 160;                // 8 jobs x 32 k-rows
                    for (int i = tid; i < 1024; i += 256) {
                        int k = j8 * 32 + (i >> 5), b = i & 31;
                        int tok = g_tok[(t + 1) * Bz + b];
                        g_xT[k * 32 + b] = emb[tok * Ee + k];
                    }
                }
            } else {
                // (vt 0..9, ds 0..7, bh 0..1): 16 b, K=64
                float* os = sh;                        // [64][pitch 20]
                int vt = job % 10, ds = (job / 10) & 7, bh = job / 80;
                for (int i = tid; i < 1024; i += 256) {
                    int b = i >> 6, dl = i & 63;       // b 0..15 local
                    int gb = bh * 16 + b;
                    int d = ds * 64 + dl;
                    float s = bc[d];
#pragma unroll
                    for (int p = 0; p < 8; p++)
                        s += g_op[((size_t)p * Bz + gb) * Dd + d];
                    float o = tanh_fast(s);
                    os[dl * 20 + b] = o;
                    if (vt == 0) g_xT[(size_t)(256 + d) * 32 + gb] = o;   // o_prevT
                }
                __syncthreads();
                int jj = tid & 63, bq = tid >> 6;      // 4 bq x 4 b
                int v = vt * 64 + jj;
                bool ok = (v < Vv);
                const float* Wp = Wout + (size_t)(ds * 64) * Vv + (ok ? v : 0);
                float acc[4];
#pragma unroll
                for (int i = 0; i < 4; i++) acc[i] = 0.0f;
#pragma unroll 16
                for (int kk = 0; kk < 64; kk++) {
                    float w = Wp[(size_t)kk * Vv];
                    float4 x0 = *(float4*)&os[kk * 20 + bq * 4];
                    acc[0] += w * x0.x; acc[1] += w * x0.y;
                    acc[2] += w * x0.z; acc[3] += w * x0.w;
                }
                if (ok) {
#pragma unroll
                    for (int i = 0; i < 4; i++) {
                        int b = bh * 16 + bq * 4 + i;
                        atomicAdd(&out_logits[((size_t)b * NSTEP + t) * Vv + v], acc[i]);
                    }
                }
            }
            __syncthreads();
        }
        gsync(nblk);
    }
}

// ----------------------------- launch ---------------------------------------
extern "C" void kernel_launch(void* const* d_in, const int* in_sizes, int n_in,
                              void* d_out, int out_size) {
    const float* enc  = (const float*)d_in[0];
    const int*   tgt  = (const int*)d_in[1];         // int32 or int64, autodetected
    const float* emb  = (const float*)d_in[2];
    const float* Wih  = (const float*)d_in[3];
    const float* bih  = (const float*)d_in[4];
    const float* Whh  = (const float*)d_in[5];
    const float* bhh  = (const float*)d_in[6];
    const float* Wh   = (const float*)d_in[7];
    const float* Wvw  = (const float*)d_in[8];
    const float* vvec = (const float*)d_in[9];
    const float* Wc   = (const float*)d_in[10];
    const float* bc   = (const float*)d_in[11];
    const float* Wout = (const float*)d_in[12];
    const float* bout = (const float*)d_in[13];

    float* out_logits = (float*)d_out;                           // (32,191,600)
    float* out_alpha  = out_logits + (size_t)Bz * NSTEP * Vv;    // (32,191,384)

    int dev = 0;
    cudaGetDevice(&dev);
    int sms = 148;
    cudaDeviceGetAttribute(&sms, cudaDevAttrMultiProcessorCount, dev);
    int per = 0;
    cudaOccupancyMaxActiveBlocksPerMultiprocessor(&per, k_all, 256, 0);
    if (per < 1) per = 1;
    if (per > 2) per = 2;
    int nblk = sms * per;                            // one resident wave

    k_all<<<nblk, 256>>>(enc, tgt, emb, Wih, bih, Whh, bhh, Wh, Wvw, vvec,
                         Wc, bc, Wout, bout, out_logits, out_alpha, nblk);
}

// round 15
// speedup vs baseline: 1.0143x; 1.0143x over previous
#include <cuda_runtime.h>
#include <cuda_bf16.h>

#define Bz 32
#define Nn 384          // H*W = 12*32
#define Cc 512
#define Dd 512
#define Ee 256
#define Vv 600
#define GJ 2048         // 4*D
#define NSTEP 191
#define EOS_TOK 130

// ----------------------------- scratch (device globals, no allocation) ------
__device__ float g_Wv[Bz * Nn * Dd];          // 24 MB   enc @ W_v, precomputed
__device__ float g_gp[8 * Bz * GJ];           // gates partials [ks][b][2048]
__device__ float g_op[8 * Bz * Dd];           // o_t partials [ks][b][d]
__device__ float g_xT[1280 * Bz];             // transposed x: [emb|oprev|hx][b]
__device__ float g_cx[Bz * Dd];
__device__ float g_q[Bz * Dd];
__device__ float g_ctxT[Cc * Bz];             // transposed context [c][b]
__device__ float g_sc[Bz * Nn];               // raw scores
__device__ int   g_tok[NSTEP * Bz];

// grid barrier state
__device__ unsigned g_count = 0;
__device__ volatile unsigned g_gen = 0;

// fast transcendentals
__device__ __forceinline__ float tanh_mufu(float x) {      // 1 MUFU, abs err ~5e-4
    float y;
    asm("tanh.approx.f32 %0, %1;" : "=f"(y) : "f"(x));
    return y;
}
__device__ __forceinline__ float tanh_fast(float x) {      // 2 MUFU, err ~1e-7
    float e = __expf(-2.0f * x);
    return __fdividef(2.0f, 1.0f + e) - 1.0f;
}
__device__ __forceinline__ float sig_fast(float x) {
    return __fdividef(1.0f, 1.0f + __expf(-x));
}

__device__ __forceinline__ void gsync(int nblk) {
    __syncthreads();
    if (threadIdx.x == 0) {
        __threadfence();
        unsigned gen = g_gen;
        unsigned t = atomicInc(&g_count, (unsigned)(nblk - 1)); // wraps at nblk-1
        if (t == (unsigned)(nblk - 1)) {
            __threadfence();
            g_gen = gen + 1;                 // release
        } else {
            while (g_gen == gen) { }         // spin (volatile load)
            __threadfence();                 // acquire
        }
    }
    __syncthreads();
}

// ============================ the whole decoder ==============================
__global__ void __launch_bounds__(256, 2) k_all(
    const float* __restrict__ enc, const int* __restrict__ tgt,
    const float* __restrict__ emb,
    const float* __restrict__ Wih, const float* __restrict__ bih,
    const float* __restrict__ Whh, const float* __restrict__ bhh,
    const float* __restrict__ Wh,  const float* __restrict__ Wvw,
    const float* __restrict__ vvec,
    const float* __restrict__ Wc,  const float* __restrict__ bc,
    const float* __restrict__ Wout,const float* __restrict__ bout,
    float* __restrict__ out_logits, float* __restrict__ out_alpha, int nblk)
{
    __shared__ float sh[6144];                       // 24 KB, reused per phase
    const int tid = threadIdx.x;
    const int bid = blockIdx.x;

    // -------------------- prologue: Wv GEMM + init + tokens -----------------
    for (int job = bid; job < 399; job += nblk) {
        if (job < 384) {
            int bm = job >> 2, bn = job & 3;
            int tm = tid / 16, tn = tid % 16;
            float acc[8][8];
#pragma unroll
            for (int i = 0; i < 8; i++)
#pragma unroll
                for (int j = 0; j < 8; j++) acc[i][j] = 0.0f;
            const float* Ag = enc + (size_t)(bm * 128) * 512;
            const float* Bg = Wvw + bn * 128;
            float* As = sh;            // [8][128]
            float* Bs = sh + 1024;     // [8][128]
            for (int k0 = 0; k0 < 512; k0 += 8) {
                {
                    int r = tid >> 1, s = tid & 1;
                    float4 a = *(const float4*)(Ag + (size_t)r * 512 + k0 + s * 4);
                    As[(s * 4 + 0) * 128 + r] = a.x; As[(s * 4 + 1) * 128 + r] = a.y;
                    As[(s * 4 + 2) * 128 + r] = a.z; As[(s * 4 + 3) * 128 + r] = a.w;
                }
                {
                    int kk = tid >> 5, c4 = tid & 31;
                    float4 bv = *(const float4*)(Bg + (size_t)(k0 + kk) * 512 + c4 * 4);
                    *(float4*)&Bs[kk * 128 + c4 * 4] = bv;
                }
                __syncthreads();
#pragma unroll
                for (int kk = 0; kk < 8; kk++) {
                    float a[8], b[8];
                    *(float4*)(a)     = *(float4*)&As[kk * 128 + tm * 8];
                    *(float4*)(a + 4) = *(float4*)&As[kk * 128 + tm * 8 + 4];
                    *(float4*)(b)     = *(float4*)&Bs[kk * 128 + tn * 8];
                    *(float4*)(b + 4) = *(float4*)&Bs[kk * 128 + tn * 8 + 4];
#pragma unroll
                    for (int i = 0; i < 8; i++)
#pragma unroll
                        for (int j = 0; j < 8; j++) acc[i][j] += a[i] * b[j];
                }
                __syncthreads();
            }
            float* Cg = g_Wv + (size_t)(bm * 128) * 512 + bn * 128;
#pragma unroll
            for (int i = 0; i < 8; i++) {
                int r = tm * 8 + i;
#pragma unroll
                for (int j = 0; j < 8; j += 4) {
                    float4 o = make_float4(acc[i][j], acc[i][j+1], acc[i][j+2], acc[i][j+3]);
                    *(float4*)(Cg + (size_t)r * 512 + tn * 8 + j) = o;
                }
            }
        } else if (job == 384) {
            // token precompute (int64/int32 autodetect: int64 high words are 0)
            if (tid == 0) {
                int nz = 0;
                for (int i = 1; i < 64; i += 2) nz |= tgt[i];
                ((int*)sh)[0] = (nz == 0) ? 1 : 0;
            }
            __syncthreads();
            int is64 = ((int*)sh)[0];
            if (tid < Bz) {
                int b = tid, fin = 0;
                g_tok[b] = 0;                         // sos
                for (int t = 0; t < NSTEP - 1; t++) {
                    int idx = b * 192 + t + 1;
                    int nt = is64 ? tgt[idx * 2] : tgt[idx];
                    fin |= (nt == EOS_TOK);
                    g_tok[(t + 1) * Bz + b] = fin ? 0 : nt;
                }
            }
        } else {
            int base = (job - 385) * 4096;            // 14 jobs x 4096 = 57344
            for (int i = tid; i < 4096; i += 256) {
                int idx = base + i;
                if (idx < 40960)        g_xT[idx] = 0.0f;      // emb(0)=0, oprev=0, hx=0
                else if (idx < 57344)   g_cx[idx - 40960] = 0.0f;
            }
        }
        __syncthreads();
    }
    gsync(nblk);

    // ============================== step loop ===============================
    for (int t = 0; t < NSTEP; t++) {

        // ---- gates split-K GEMM: 256 jobs (32 jt x 8 ks), 4j-wide LDG.128 ----
        for (int job = bid; job < 256; job += nblk) {
            int jt = job & 31, ks = job >> 5;
            int kbase, klen;
            if (ks < 4) { kbase = ks * 192;             klen = 192; }
            else        { kbase = 768 + (ks - 4) * 128; klen = 128; }
            float* xs = sh;                            // [klen][32]
            for (int i4 = tid; i4 < klen * 8; i4 += 256) {
                int kk = i4 >> 3, b4 = i4 & 7;
                float4 v = ((const float4*)(g_xT + (size_t)(kbase + kk) * 32))[b4];
                ((float4*)(xs + kk * 32))[b4] = v;
            }
            __syncthreads();
            int jg = tid & 15, bq = tid >> 4;          // 4 j each, 2 b each
            int j = jt * 64 + jg * 4;
            const float* Wbase = (ks < 4) ? (Wih + (size_t)kbase * GJ + j)
                                          : (Whh + (size_t)(kbase - 768) * GJ + j);
            const float4* Wp4 = (const float4*)Wbase;
            float a0x=0,a0y=0,a0z=0,a0w=0, a1x=0,a1y=0,a1z=0,a1w=0;
#pragma unroll 16
            for (int kk = 0; kk < klen; kk++) {
                float4 w = Wp4[(size_t)kk * (GJ / 4)];
                float2 x = *(const float2*)&xs[kk * 32 + bq * 2];
                a0x += x.x * w.x; a0y += x.x * w.y; a0z += x.x * w.z; a0w += x.x * w.w;
                a1x += x.y * w.x; a1y += x.y * w.y; a1z += x.y * w.z; a1w += x.y * w.w;
            }
            *(float4*)&g_gp[((size_t)ks * Bz + bq * 2 + 0) * GJ + j] = make_float4(a0x,a0y,a0z,a0w);
            *(float4*)&g_gp[((size_t)ks * Bz + bq * 2 + 1) * GJ + j] = make_float4(a1x,a1y,a1z,a1w);
            __syncthreads();
        }
        gsync(nblk);

        // ---- LSTM elementwise (reduce 8 partials) + zero q/ctxT, write hxT ----
        for (int idx = bid * 256 + tid; idx < 16384; idx += nblk * 256) {
            int d = idx & 511;
            int b = idx >> 9;
            float gi = bih[d] + bhh[d];
            float gf = bih[d + 512] + bhh[d + 512];
            float gg = bih[d + 1024] + bhh[d + 1024];
            float go = bih[d + 1536] + bhh[d + 1536];
#pragma unroll
            for (int s = 0; s < 8; s++) {
                const float* gp = g_gp + ((size_t)s * Bz + b) * GJ;
                gi += gp[d];
                gf += gp[d + 512];
                gg += gp[d + 1024];
                go += gp[d + 1536];
            }
            float c = g_cx[idx];
            c = sig_fast(gf) * c + sig_fast(gi) * tanh_fast(gg);
            float h = sig_fast(go) * tanh_fast(c);
            g_cx[idx] = c;
            g_xT[(768 + d) * 32 + b] = h;            // transposed hx
            g_q[idx] = 0.0f;
            g_ctxT[idx] = 0.0f;
        }
        gsync(nblk);

        // ---- q = hx @ W_h: 128 jobs (8 dt x 16 ks of K=32), atomic accum ----
        for (int job = bid; job < 128; job += nblk) {
            int dt = job & 7, ks = job >> 3;
            float* xs = sh;                            // [32][32]
            {
                int kk = tid >> 3, b4 = tid & 7;
                float4 v = ((const float4*)(g_xT + (size_t)(768 + ks * 32 + kk) * 32))[b4];
                ((float4*)(xs + kk * 32))[b4] = v;
            }
            __syncthreads();
            int dl = tid & 63, bq = tid >> 6;
            int d = dt * 64 + dl;
            const float* Wp = Wh + (size_t)(ks * 32) * Dd + d;
            float acc[8];
#pragma unroll
            for (int i = 0; i < 8; i++) acc[i] = 0.0f;
#pragma unroll 16
            for (int kk = 0; kk < 32; kk++) {
                float w = Wp[(size_t)kk * Dd];
                float4 x0 = *(float4*)&xs[kk * 32 + bq * 8];
                float4 x1 = *(float4*)&xs[kk * 32 + bq * 8 + 4];
                acc[0] += w * x0.x; acc[1] += w * x0.y; acc[2] += w * x0.z; acc[3] += w * x0.w;
                acc[4] += w * x1.x; acc[5] += w * x1.y; acc[6] += w * x1.z; acc[7] += w * x1.w;
            }
#pragma unroll
            for (int i = 0; i < 8; i++)
                atomicAdd(&g_q[(bq * 8 + i) * Dd + d], acc[i]);
            __syncthreads();
        }
        gsync(nblk);

        // ---- scores: 608 jobs (19 tiles x 32 b) = exactly 2 rounds ----
        for (int job = bid; job < 608; job += nblk) {
            int nt = job % 19, b = job / 19;
            float* qs = sh;
            float* vs = sh + 512;
            qs[tid] = g_q[b * Dd + tid];
            qs[tid + 256] = g_q[b * Dd + tid + 256];
            vs[tid] = vvec[tid];
            vs[tid + 256] = vvec[tid + 256];
            __syncthreads();
            int w = tid >> 5, lane = tid & 31;
            int n0 = nt * 20;
            int cnt = (nt == 18) ? 24 : 20;
            const float4* q4 = (const float4*)qs;
            const float4* v4 = (const float4*)vs;
            for (int r = w; r < cnt; r += 8) {
                int n = n0 + r;
                const float4* wv = (const float4*)(g_Wv + (size_t)(b * Nn + n) * Dd);
                float acc = 0.0f;
#pragma unroll
                for (int i = 0; i < 4; i++) {
                    int id = i * 32 + lane;
                    float4 a = wv[id], q = q4[id], v = v4[id];
                    acc += tanh_mufu(a.x + q.x) * v.x;
                    acc += tanh_mufu(a.y + q.y) * v.y;
                    acc += tanh_mufu(a.z + q.z) * v.z;
                    acc += tanh_mufu(a.w + q.w) * v.w;
                }
#pragma unroll
                for (int off = 16; off > 0; off >>= 1)
                    acc += __shfl_xor_sync(0xffffffffu, acc, off);
                if (lane == 0) g_sc[b * Nn + n] = acc;
            }
            __syncthreads();
        }
        gsync(nblk);

        // ---- softmax + context + alpha: 256 jobs (8 strips x 32 b) ----
        for (int job = bid; job < 256; job += nblk) {
            int st = job & 7, b = job >> 3;
            float* al = sh;                            // [384]
            float* red = sh + 384;                     // [256]
            float m = -1e30f;
            for (int i = tid; i < Nn; i += 256) {
                float s = g_sc[b * Nn + i];
                al[i] = s;
                m = fmaxf(m, s);
            }
            red[tid] = m; __syncthreads();
            for (int o = 128; o > 0; o >>= 1) {
                if (tid < o) red[tid] = fmaxf(red[tid], red[tid + o]);
                __syncthreads();
            }
            m = red[0];
            __syncthreads();
            float sum = 0.0f;
            for (int i = tid; i < Nn; i += 256) {
                float e = __expf(al[i] - m);
                al[i] = e;
                sum += e;
            }
            red[tid] = sum; __syncthreads();
            for (int o = 128; o > 0; o >>= 1) {
                if (tid < o) red[tid] += red[tid + o];
                __syncthreads();
            }
            float inv = __fdividef(1.0f, red[0]);
            __syncthreads();
            for (int i = tid; i < Nn; i += 256) al[i] *= inv;
            __syncthreads();

            if (st == 0) {
                float* ap = out_alpha + ((size_t)b * NSTEP + t) * Nn;
                for (int i = tid; i < Nn; i += 256) ap[i] = al[i];
            }
            // context partial: strip of 48 n, 2 ways of 24 n
            int c4 = tid & 127, way = tid >> 7;
            const float4* ep = (const float4*)enc + (size_t)b * Nn * 128 + c4;
            float4 acc = make_float4(0.f, 0.f, 0.f, 0.f);
            int n0 = st * 48 + way * 24;
#pragma unroll 8
            for (int n = n0; n < n0 + 24; n++) {
                float a = al[n];
                float4 ev = ep[(size_t)n * 128];
                acc.x += a * ev.x; acc.y += a * ev.y;
                acc.z += a * ev.z; acc.w += a * ev.w;
            }
            int c = c4 * 4;
            atomicAdd(&g_ctxT[(size_t)(c + 0) * 32 + b], acc.x);
            atomicAdd(&g_ctxT[(size_t)(c + 1) * 32 + b], acc.y);
            atomicAdd(&g_ctxT[(size_t)(c + 2) * 32 + b], acc.z);
            atomicAdd(&g_ctxT[(size_t)(c + 3) * 32 + b], acc.w);
            __syncthreads();
        }
        gsync(nblk);

        // ---- o_t partials (4d-wide LDG.128) + logits bias init: 203 jobs ----
        for (int job = bid; job < 203; job += nblk) {
            if (job >= 128) {
                int idx = (job - 128) * 256 + tid;     // < 32*600 = 19200
                if (idx < Bz * Vv) {
                    int b = idx / Vv, v = idx % Vv;
                    out_logits[((size_t)b * NSTEP + t) * Vv + v] = bout[v];
                }
            } else {
                // (dt 0..7, ks 0..7, bh 0..1): 16 b per job, K=128, 4d-wide
                float* xs = sh;                        // [128][16]
                int dt = job & 7, ks = (job >> 3) & 7, bh = job >> 6;
                for (int i = tid; i < 2048; i += 256) {
                    int kk = i >> 4, b4 = i & 15;
                    int k = ks * 128 + kk;
                    float val;
                    if (k < 512) val = g_xT[(size_t)(768 + k) * 32 + bh * 16 + b4];
                    else         val = g_ctxT[(size_t)(k - 512) * 32 + bh * 16 + b4];
                    xs[kk * 16 + b4] = val;
                }
                __syncthreads();
                int jg = tid & 15, bq = tid >> 4;      // 4 d each, 1 b each (16 b)
                int d = dt * 64 + jg * 4;
                const float4* Wp4 = (const float4*)(Wc + (size_t)(ks * 128) * Dd + d);
                float ax = 0, ay = 0, az = 0, aw = 0;
#pragma unroll 16
                for (int kk = 0; kk < 128; kk++) {
                    float4 w = Wp4[(size_t)kk * (Dd / 4)];
                    float x = xs[kk * 16 + bq];
                    ax += x * w.x; ay += x * w.y; az += x * w.z; aw += x * w.w;
                }
                *(float4*)&g_op[((size_t)ks * Bz + bh * 16 + bq) * Dd + d] =
                    make_float4(ax, ay, az, aw);
            }
            __syncthreads();
        }
        gsync(nblk);

        // ---- logits + o_prevT persist + embT(t+1) prefetch: 168 jobs ----
        for (int job = bid; job < 168; job += nblk) {
            if (job >= 160) {
                if (t + 1 < NSTEP) {
                    int j8 = job - 160;                // 8 jobs x 32 k-rows
                    for (int i = tid; i < 1024; i += 256) {
                        int k = j8 * 32 + (i >> 5), b = i & 31;
                        int tok = g_tok[(t + 1) * Bz + b];
                        g_xT[k * 32 + b] = emb[tok * Ee + k];
                    }
                }
            } else {
                // (vt 0..9, ds 0..7, bh 0..1): 16 b, K=64
                float* os = sh;                        // [64][pitch 20]
                int vt = job % 10, ds = (job / 10) & 7, bh = job / 80;
                for (int i = tid; i < 1024; i += 256) {
                    int b = i >> 6, dl = i & 63;       // b 0..15 local
                    int gb = bh * 16 + b;
                    int d = ds * 64 + dl;
                    float s = bc[d];
#pragma unroll
                    for (int p = 0; p < 8; p++)
                        s += g_op[((size_t)p * Bz + gb) * Dd + d];
                    float o = tanh_fast(s);
                    os[dl * 20 + b] = o;
                    if (vt == 0) g_xT[(size_t)(256 + d) * 32 + gb] = o;   // o_prevT
                }
                __syncthreads();
                int jj = tid & 63, bq = tid >> 6;      // 4 bq x 4 b
                int v = vt * 64 + jj;
                bool ok = (v < Vv);
                const float* Wp = Wout + (size_t)(ds * 64) * Vv + (ok ? v : 0);
                float acc[4];
#pragma unroll
                for (int i = 0; i < 4; i++) acc[i] = 0.0f;
#pragma unroll 16
                for (int kk = 0; kk < 64; kk++) {
                    float w = Wp[(size_t)kk * Vv];
                    float4 x0 = *(float4*)&os[kk * 20 + bq * 4];
                    acc[0] += w * x0.x; acc[1] += w * x0.y;
                    acc[2] += w * x0.z; acc[3] += w * x0.w;
                }
                if (ok) {
#pragma unroll
                    for (int i = 0; i < 4; i++) {
                        int b = bh * 16 + bq * 4 + i;
                        atomicAdd(&out_logits[((size_t)b * NSTEP + t) * Vv + v], acc[i]);
                    }
                }
            }
            __syncthreads();
        }
        gsync(nblk);
    }
}

// ----------------------------- launch ---------------------------------------
extern "C" void kernel_launch(void* const* d_in, const int* in_sizes, int n_in,
                              void* d_out, int out_size) {
    const float* enc  = (const float*)d_in[0];
    const int*   tgt  = (const int*)d_in[1];         // int32 or int64, autodetected
    const float* emb  = (const float*)d_in[2];
    const float* Wih  = (const float*)d_in[3];
    const float* bih  = (const float*)d_in[4];
    const float* Whh  = (const float*)d_in[5];
    const float* bhh  = (const float*)d_in[6];
    const float* Wh   = (const float*)d_in[7];
    const float* Wvw  = (const float*)d_in[8];
    const float* vvec = (const float*)d_in[9];
    const float* Wc   = (const float*)d_in[10];
    const float* bc   = (const float*)d_in[11];
    const float* Wout = (const float*)d_in[12];
    const float* bout = (const float*)d_in[13];

    float* out_logits = (float*)d_out;                           // (32,191,600)
    float* out_alpha  = out_logits + (size_t)Bz * NSTEP * Vv;    // (32,191,384)

    int dev = 0;
    cudaGetDevice(&dev);
    int sms = 148;
    cudaDeviceGetAttribute(&sms, cudaDevAttrMultiProcessorCount, dev);
    int per = 0;
    cudaOccupancyMaxActiveBlocksPerMultiprocessor(&per, k_all, 256, 0);
    if (per < 1) per = 1;
    if (per > 2) per = 2;
    int nblk = sms * per;                            // one resident wave

    k_all<<<nblk, 256>>>(enc, tgt, emb, Wih, bih, Whh, bhh, Wh, Wvw, vvec,
                         Wc, bc, Wout, bout, out_logits, out_alpha, nblk);
}

// round 16
// speedup vs baseline: 1.0215x; 1.0071x over previous
#include <cuda_runtime.h>
#include <cuda_bf16.h>

#define Bz 32
#define Nn 384          // H*W = 12*32
#define Cc 512
#define Dd 512
#define Ee 256
#define Vv 600
#define GJ 2048         // 4*D
#define NSTEP 191
#define EOS_TOK 130

// ----------------------------- scratch (device globals, no allocation) ------
__device__ float g_Wv[Bz * Nn * Dd];          // 24 MB   enc @ W_v, precomputed
__device__ float g_gp[8 * Bz * GJ];           // gates partials [ks][b][2048]
__device__ float g_op[8 * Bz * Dd];           // o_t partials [ks][b][d]
__device__ float g_xT[1280 * Bz];             // transposed x: [emb|oprev|hx][b]
__device__ float g_cx[Bz * Dd];
__device__ float g_q[Bz * Dd];
__device__ float g_ctxT[Cc * Bz];             // transposed context [c][b]
__device__ float g_sc[Bz * Nn];               // raw scores
__device__ int   g_tok[NSTEP * Bz];

// grid barrier state
__device__ unsigned g_count = 0;
__device__ volatile unsigned g_gen = 0;

// fast transcendentals
__device__ __forceinline__ float tanh_mufu(float x) {      // 1 MUFU, abs err ~5e-4
    float y;
    asm("tanh.approx.f32 %0, %1;" : "=f"(y) : "f"(x));
    return y;
}
// division-free reciprocal: bit-hack seed + 3 Newton steps (FMA pipe only)
__device__ __forceinline__ float rcp_nr(float q) {
    float r = __int_as_float(0x7EF311C3 - __float_as_int(q));
    r = r * (2.0f - q * r);
    r = r * (2.0f - q * r);
    r = r * (2.0f - q * r);
    return r;
}
// Pade(7,6) tanh, FMA-pipe only. p/q >= 1 for |x| >= 4.97 so clamp is exact.
__device__ __forceinline__ float tanh_poly(float x) {
    float x2 = x * x;
    float p = x * (135135.0f + x2 * (17325.0f + x2 * (378.0f + x2)));
    float q = 135135.0f + x2 * (62370.0f + x2 * (3150.0f + 28.0f * x2));
    float y = p * rcp_nr(q);
    return fminf(1.0f, fmaxf(-1.0f, y));
}
__device__ __forceinline__ float tanh_fast(float x) {      // 2 MUFU, err ~1e-7
    float e = __expf(-2.0f * x);
    return __fdividef(2.0f, 1.0f + e) - 1.0f;
}
__device__ __forceinline__ float sig_fast(float x) {
    return __fdividef(1.0f, 1.0f + __expf(-x));
}

__device__ __forceinline__ void gsync(int nblk) {
    __syncthreads();
    if (threadIdx.x == 0) {
        __threadfence();
        unsigned gen = g_gen;
        unsigned t = atomicInc(&g_count, (unsigned)(nblk - 1)); // wraps at nblk-1
        if (t == (unsigned)(nblk - 1)) {
            __threadfence();
            g_gen = gen + 1;                 // release
        } else {
            while (g_gen == gen) { }         // spin (volatile load)
            __threadfence();                 // acquire
        }
    }
    __syncthreads();
}

// ============================ the whole decoder ==============================
__global__ void __launch_bounds__(256, 2) k_all(
    const float* __restrict__ enc, const int* __restrict__ tgt,
    const float* __restrict__ emb,
    const float* __restrict__ Wih, const float* __restrict__ bih,
    const float* __restrict__ Whh, const float* __restrict__ bhh,
    const float* __restrict__ Wh,  const float* __restrict__ Wvw,
    const float* __restrict__ vvec,
    const float* __restrict__ Wc,  const float* __restrict__ bc,
    const float* __restrict__ Wout,const float* __restrict__ bout,
    float* __restrict__ out_logits, float* __restrict__ out_alpha, int nblk)
{
    __shared__ float sh[6144];                       // 24 KB, reused per phase
    const int tid = threadIdx.x;
    const int bid = blockIdx.x;

    // -------------------- prologue: Wv GEMM + init + tokens -----------------
    for (int job = bid; job < 399; job += nblk) {
        if (job < 384) {
            int bm = job >> 2, bn = job & 3;
            int tm = tid / 16, tn = tid % 16;
            float acc[8][8];
#pragma unroll
            for (int i = 0; i < 8; i++)
#pragma unroll
                for (int j = 0; j < 8; j++) acc[i][j] = 0.0f;
            const float* Ag = enc + (size_t)(bm * 128) * 512;
            const float* Bg = Wvw + bn * 128;
            float* As = sh;            // [8][128]
            float* Bs = sh + 1024;     // [8][128]
            for (int k0 = 0; k0 < 512; k0 += 8) {
                {
                    int r = tid >> 1, s = tid & 1;
                    float4 a = *(const float4*)(Ag + (size_t)r * 512 + k0 + s * 4);
                    As[(s * 4 + 0) * 128 + r] = a.x; As[(s * 4 + 1) * 128 + r] = a.y;
                    As[(s * 4 + 2) * 128 + r] = a.z; As[(s * 4 + 3) * 128 + r] = a.w;
                }
                {
                    int kk = tid >> 5, c4 = tid & 31;
                    float4 bv = *(const float4*)(Bg + (size_t)(k0 + kk) * 512 + c4 * 4);
                    *(float4*)&Bs[kk * 128 + c4 * 4] = bv;
                }
                __syncthreads();
#pragma unroll
                for (int kk = 0; kk < 8; kk++) {
                    float a[8], b[8];
                    *(float4*)(a)     = *(float4*)&As[kk * 128 + tm * 8];
                    *(float4*)(a + 4) = *(float4*)&As[kk * 128 + tm * 8 + 4];
                    *(float4*)(b)     = *(float4*)&Bs[kk * 128 + tn * 8];
                    *(float4*)(b + 4) = *(float4*)&Bs[kk * 128 + tn * 8 + 4];
#pragma unroll
                    for (int i = 0; i < 8; i++)
#pragma unroll
                        for (int j = 0; j < 8; j++) acc[i][j] += a[i] * b[j];
                }
                __syncthreads();
            }
            float* Cg = g_Wv + (size_t)(bm * 128) * 512 + bn * 128;
#pragma unroll
            for (int i = 0; i < 8; i++) {
                int r = tm * 8 + i;
#pragma unroll
                for (int j = 0; j < 8; j += 4) {
                    float4 o = make_float4(acc[i][j], acc[i][j+1], acc[i][j+2], acc[i][j+3]);
                    *(float4*)(Cg + (size_t)r * 512 + tn * 8 + j) = o;
                }
            }
        } else if (job == 384) {
            // token precompute (int64/int32 autodetect: int64 high words are 0)
            if (tid == 0) {
                int nz = 0;
                for (int i = 1; i < 64; i += 2) nz |= tgt[i];
                ((int*)sh)[0] = (nz == 0) ? 1 : 0;
            }
            __syncthreads();
            int is64 = ((int*)sh)[0];
            if (tid < Bz) {
                int b = tid, fin = 0;
                g_tok[b] = 0;                         // sos
                for (int t = 0; t < NSTEP - 1; t++) {
                    int idx = b * 192 + t + 1;
                    int nt = is64 ? tgt[idx * 2] : tgt[idx];
                    fin |= (nt == EOS_TOK);
                    g_tok[(t + 1) * Bz + b] = fin ? 0 : nt;
                }
            }
        } else {
            int base = (job - 385) * 4096;            // 14 jobs x 4096 = 57344
            for (int i = tid; i < 4096; i += 256) {
                int idx = base + i;
                if (idx < 40960)        g_xT[idx] = 0.0f;      // emb(0)=0, oprev=0, hx=0
                else if (idx < 57344)   g_cx[idx - 40960] = 0.0f;
            }
        }
        __syncthreads();
    }
    gsync(nblk);

    // ============================== step loop ===============================
    for (int t = 0; t < NSTEP; t++) {

        // ---- gates split-K GEMM: 256 jobs (32 jt x 8 ks) ----
        for (int job = bid; job < 256; job += nblk) {
            int jt = job & 31, ks = job >> 5;
            int kbase, klen;
            if (ks < 4) { kbase = ks * 192;             klen = 192; }
            else        { kbase = 768 + (ks - 4) * 128; klen = 128; }
            float* xs = sh;                            // [klen][32]
            for (int i4 = tid; i4 < klen * 8; i4 += 256) {
                int kk = i4 >> 3, b4 = i4 & 7;
                float4 v = ((const float4*)(g_xT + (size_t)(kbase + kk) * 32))[b4];
                ((float4*)(xs + kk * 32))[b4] = v;
            }
            __syncthreads();
            int jj = tid & 63, bq = tid >> 6;
            int j = jt * 64 + jj;
            const float* Wp = (ks < 4) ? (Wih + (size_t)kbase * GJ + j)
                                       : (Whh + (size_t)(kbase - 768) * GJ + j);
            float acc[8];
#pragma unroll
            for (int i = 0; i < 8; i++) acc[i] = 0.0f;
#pragma unroll 16
            for (int kk = 0; kk < klen; kk++) {
                float w = Wp[(size_t)kk * GJ];
                float4 x0 = *(float4*)&xs[kk * 32 + bq * 8];
                float4 x1 = *(float4*)&xs[kk * 32 + bq * 8 + 4];
                acc[0] += w * x0.x; acc[1] += w * x0.y; acc[2] += w * x0.z; acc[3] += w * x0.w;
                acc[4] += w * x1.x; acc[5] += w * x1.y; acc[6] += w * x1.z; acc[7] += w * x1.w;
            }
#pragma unroll
            for (int i = 0; i < 8; i++)
                g_gp[((size_t)ks * Bz + bq * 8 + i) * GJ + j] = acc[i];
            __syncthreads();
        }
        gsync(nblk);

        // ---- LSTM elementwise (reduce 8 partials) + zero q/ctxT, write hxT ----
        for (int idx = bid * 256 + tid; idx < 16384; idx += nblk * 256) {
            int d = idx & 511;
            int b = idx >> 9;
            float gi = bih[d] + bhh[d];
            float gf = bih[d + 512] + bhh[d + 512];
            float gg = bih[d + 1024] + bhh[d + 1024];
            float go = bih[d + 1536] + bhh[d + 1536];
#pragma unroll
            for (int s = 0; s < 8; s++) {
                const float* gp = g_gp + ((size_t)s * Bz + b) * GJ;
                gi += gp[d];
                gf += gp[d + 512];
                gg += gp[d + 1024];
                go += gp[d + 1536];
            }
            float c = g_cx[idx];
            c = sig_fast(gf) * c + sig_fast(gi) * tanh_fast(gg);
            float h = sig_fast(go) * tanh_fast(c);
            g_cx[idx] = c;
            g_xT[(768 + d) * 32 + b] = h;            // transposed hx
            g_q[idx] = 0.0f;
            g_ctxT[idx] = 0.0f;
        }
        gsync(nblk);

        // ---- q = hx @ W_h: 128 jobs (8 dt x 16 ks of K=32), atomic accum ----
        for (int job = bid; job < 128; job += nblk) {
            int dt = job & 7, ks = job >> 3;
            float* xs = sh;                            // [32][32]
            {
                int kk = tid >> 3, b4 = tid & 7;
                float4 v = ((const float4*)(g_xT + (size_t)(768 + ks * 32 + kk) * 32))[b4];
                ((float4*)(xs + kk * 32))[b4] = v;
            }
            __syncthreads();
            int dl = tid & 63, bq = tid >> 6;
            int d = dt * 64 + dl;
            const float* Wp = Wh + (size_t)(ks * 32) * Dd + d;
            float acc[8];
#pragma unroll
            for (int i = 0; i < 8; i++) acc[i] = 0.0f;
#pragma unroll 16
            for (int kk = 0; kk < 32; kk++) {
                float w = Wp[(size_t)kk * Dd];
                float4 x0 = *(float4*)&xs[kk * 32 + bq * 8];
                float4 x1 = *(float4*)&xs[kk * 32 + bq * 8 + 4];
                acc[0] += w * x0.x; acc[1] += w * x0.y; acc[2] += w * x0.z; acc[3] += w * x0.w;
                acc[4] += w * x1.x; acc[5] += w * x1.y; acc[6] += w * x1.z; acc[7] += w * x1.w;
            }
#pragma unroll
            for (int i = 0; i < 8; i++)
                atomicAdd(&g_q[(bq * 8 + i) * Dd + d], acc[i]);
            __syncthreads();
        }
        gsync(nblk);

        // ---- scores: 608 jobs (19 tiles x 32 b), hybrid MUFU/FMA tanh ----
        for (int job = bid; job < 608; job += nblk) {
            int nt = job % 19, b = job / 19;
            float* qs = sh;
            float* vs = sh + 512;
            qs[tid] = g_q[b * Dd + tid];
            qs[tid + 256] = g_q[b * Dd + tid + 256];
            vs[tid] = vvec[tid];
            vs[tid + 256] = vvec[tid + 256];
            __syncthreads();
            int w = tid >> 5, lane = tid & 31;
            int n0 = nt * 20;
            int cnt = (nt == 18) ? 24 : 20;
            const float4* q4 = (const float4*)qs;
            const float4* v4 = (const float4*)vs;
            for (int r = w; r < cnt; r += 8) {
                int n = n0 + r;
                const float4* wv = (const float4*)(g_Wv + (size_t)(b * Nn + n) * Dd);
                float acc = 0.0f;
#pragma unroll
                for (int i = 0; i < 4; i++) {
                    int id = i * 32 + lane;
                    float4 a = wv[id], q = q4[id], v = v4[id];
                    // 2 lanes on MUFU pipe, 2 lanes on FMA pipe -> concurrent
                    acc += tanh_mufu(a.x + q.x) * v.x;
                    acc += tanh_poly(a.y + q.y) * v.y;
                    acc += tanh_mufu(a.z + q.z) * v.z;
                    acc += tanh_poly(a.w + q.w) * v.w;
                }
#pragma unroll
                for (int off = 16; off > 0; off >>= 1)
                    acc += __shfl_xor_sync(0xffffffffu, acc, off);
                if (lane == 0) g_sc[b * Nn + n] = acc;
            }
            __syncthreads();
        }
        gsync(nblk);

        // ---- softmax + context + alpha: 256 jobs (8 strips x 32 b) ----
        for (int job = bid; job < 256; job += nblk) {
            int st = job & 7, b = job >> 3;
            float* al = sh;                            // [384]
            float* red = sh + 384;                     // [256]
            float m = -1e30f;
            for (int i = tid; i < Nn; i += 256) {
                float s = g_sc[b * Nn + i];
                al[i] = s;
                m = fmaxf(m, s);
            }
            red[tid] = m; __syncthreads();
            for (int o = 128; o > 0; o >>= 1) {
                if (tid < o) red[tid] = fmaxf(red[tid], red[tid + o]);
                __syncthreads();
            }
            m = red[0];
            __syncthreads();
            float sum = 0.0f;
            for (int i = tid; i < Nn; i += 256) {
                float e = __expf(al[i] - m);
                al[i] = e;
                sum += e;
            }
            red[tid] = sum; __syncthreads();
            for (int o = 128; o > 0; o >>= 1) {
                if (tid < o) red[tid] += red[tid + o];
                __syncthreads();
            }
            float inv = __fdividef(1.0f, red[0]);
            __syncthreads();
            for (int i = tid; i < Nn; i += 256) al[i] *= inv;
            __syncthreads();

            if (st == 0) {
                float* ap = out_alpha + ((size_t)b * NSTEP + t) * Nn;
                for (int i = tid; i < Nn; i += 256) ap[i] = al[i];
            }
            // context partial: strip of 48 n, 2 ways of 24 n
            int c4 = tid & 127, way = tid >> 7;
            const float4* ep = (const float4*)enc + (size_t)b * Nn * 128 + c4;
            float4 acc = make_float4(0.f, 0.f, 0.f, 0.f);
            int n0 = st * 48 + way * 24;
#pragma unroll 8
            for (int n = n0; n < n0 + 24; n++) {
                float a = al[n];
                float4 ev = ep[(size_t)n * 128];
                acc.x += a * ev.x; acc.y += a * ev.y;
                acc.z += a * ev.z; acc.w += a * ev.w;
            }
            int c = c4 * 4;
            atomicAdd(&g_ctxT[(size_t)(c + 0) * 32 + b], acc.x);
            atomicAdd(&g_ctxT[(size_t)(c + 1) * 32 + b], acc.y);
            atomicAdd(&g_ctxT[(size_t)(c + 2) * 32 + b], acc.z);
            atomicAdd(&g_ctxT[(size_t)(c + 3) * 32 + b], acc.w);
            __syncthreads();
        }
        gsync(nblk);

        // ---- o_t partials + logits bias init: 203 jobs ----
        for (int job = bid; job < 203; job += nblk) {
            if (job >= 128) {
                int idx = (job - 128) * 256 + tid;     // < 32*600 = 19200
                if (idx < Bz * Vv) {
                    int b = idx / Vv, v = idx % Vv;
                    out_logits[((size_t)b * NSTEP + t) * Vv + v] = bout[v];
                }
            } else {
                // (dt 0..7, ks 0..7, bh 0..1): 16 b per job, K=128
                float* xs = sh;                        // [128][16]
                int dt = job & 7, ks = (job >> 3) & 7, bh = job >> 6;
                for (int i = tid; i < 2048; i += 256) {
                    int kk = i >> 4, b4 = i & 15;
                    int k = ks * 128 + kk;
                    float val;
                    if (k < 512) val = g_xT[(size_t)(768 + k) * 32 + bh * 16 + b4];
                    else         val = g_ctxT[(size_t)(k - 512) * 32 + bh * 16 + b4];
                    xs[kk * 16 + b4] = val;
                }
                __syncthreads();
                int dl = tid & 63, bq = tid >> 6;      // bq 0..3, 4 b each
                int d = dt * 64 + dl;
                const float* Wp = Wc + (size_t)(ks * 128) * Dd + d;
                float acc[4];
#pragma unroll
                for (int i = 0; i < 4; i++) acc[i] = 0.0f;
#pragma unroll 16
                for (int kk = 0; kk < 128; kk++) {
                    float w = Wp[(size_t)kk * Dd];
                    float4 x0 = *(float4*)&xs[kk * 16 + bq * 4];
                    acc[0] += w * x0.x; acc[1] += w * x0.y;
                    acc[2] += w * x0.z; acc[3] += w * x0.w;
                }
#pragma unroll
                for (int i = 0; i < 4; i++)
                    g_op[((size_t)ks * Bz + bh * 16 + bq * 4 + i) * Dd + d] = acc[i];
            }
            __syncthreads();
        }
        gsync(nblk);

        // ---- logits + o_prevT persist + embT(t+1) prefetch: 168 jobs ----
        for (int job = bid; job < 168; job += nblk) {
            if (job >= 160) {
                if (t + 1 < NSTEP) {
                    int j8 = job - 160;                // 8 jobs x 32 k-rows
                    for (int i = tid; i < 1024; i += 256) {
                        int k = j8 * 32 + (i >> 5), b = i & 31;
                        int tok = g_tok[(t + 1) * Bz + b];
                        g_xT[k * 32 + b] = emb[tok * Ee + k];
                    }
                }
            } else {
                // (vt 0..9, ds 0..7, bh 0..1): 16 b, K=64
                float* os = sh;                        // [64][pitch 20]
                int vt = job % 10, ds = (job / 10) & 7, bh = job / 80;
                for (int i = tid; i < 1024; i += 256) {
                    int b = i >> 6, dl = i & 63;       // b 0..15 local
                    int gb = bh * 16 + b;
                    int d = ds * 64 + dl;
                    float s = bc[d];
#pragma unroll
                    for (int p = 0; p < 8; p++)
                        s += g_op[((size_t)p * Bz + gb) * Dd + d];
                    float o = tanh_fast(s);
                    os[dl * 20 + b] = o;
                    if (vt == 0) g_xT[(size_t)(256 + d) * 32 + gb] = o;   // o_prevT
                }
                __syncthreads();
                int jj = tid & 63, bq = tid >> 6;      // 4 bq x 4 b
                int v = vt * 64 + jj;
                bool ok = (v < Vv);
                const float* Wp = Wout + (size_t)(ds * 64) * Vv + (ok ? v : 0);
                float acc[4];
#pragma unroll
                for (int i = 0; i < 4; i++) acc[i] = 0.0f;
#pragma unroll 16
                for (int kk = 0; kk < 64; kk++) {
                    float w = Wp[(size_t)kk * Vv];
                    float4 x0 = *(float4*)&os[kk * 20 + bq * 4];
                    acc[0] += w * x0.x; acc[1] += w * x0.y;
                    acc[2] += w * x0.z; acc[3] += w * x0.w;
                }
                if (ok) {
#pragma unroll
                    for (int i = 0; i < 4; i++) {
                        int b = bh * 16 + bq * 4 + i;
                        atomicAdd(&out_logits[((size_t)b * NSTEP + t) * Vv + v], acc[i]);
                    }
                }
            }
            __syncthreads();
        }
        gsync(nblk);
    }
}

// ----------------------------- launch ---------------------------------------
extern "C" void kernel_launch(void* const* d_in, const int* in_sizes, int n_in,
                              void* d_out, int out_size) {
    const float* enc  = (const float*)d_in[0];
    const int*   tgt  = (const int*)d_in[1];         // int32 or int64, autodetected
    const float* emb  = (const float*)d_in[2];
    const float* Wih  = (const float*)d_in[3];
    const float* bih  = (const float*)d_in[4];
    const float* Whh  = (const float*)d_in[5];
    const float* bhh  = (const float*)d_in[6];
    const float* Wh   = (const float*)d_in[7];
    const float* Wvw  = (const float*)d_in[8];
    const float* vvec = (const float*)d_in[9];
    const float* Wc   = (const float*)d_in[10];
    const float* bc   = (const float*)d_in[11];
    const float* Wout = (const float*)d_in[12];
    const float* bout = (const float*)d_in[13];

    float* out_logits = (float*)d_out;                           // (32,191,600)
    float* out_alpha  = out_logits + (size_t)Bz * NSTEP * Vv;    // (32,191,384)

    int dev = 0;
    cudaGetDevice(&dev);
    int sms = 148;
    cudaDeviceGetAttribute(&sms, cudaDevAttrMultiProcessorCount, dev);
    int per = 0;
    cudaOccupancyMaxActiveBlocksPerMultiprocessor(&per, k_all, 256, 0);
    if (per < 1) per = 1;
    if (per > 2) per = 2;
    int nblk = sms * per;                            // one resident wave

    k_all<<<nblk, 256>>>(enc, tgt, emb, Wih, bih, Whh, bhh, Wh, Wvw, vvec,
                         Wc, bc, Wout, bout, out_logits, out_alpha, nblk);
}